// round 9
// baseline (speedup 1.0000x reference)
#include <cuda_runtime.h>
#include <cuda_pipeline.h>

// LIF scan — warp-local cp.async pipeline, 32-step stages x 4 slots (64 KB).
//   out[b,0,h] = 0
//   for k=1..T-1: reset=(V>1); V = 0.9V + z[b,k-1,h] - reset; out[b,k,h] = (V>1)
//
// 1 thread <-> 1 (b,h) chain; 128 blocks x 128 threads (1 CTA/SM).
// Warp owns 32 contiguous h-columns; threads cooperatively cp.async 16B
// granules (4 cols each, 8 granules/thread/stage). Warp-internal visibility
// only => __syncwarp per stage, no __syncthreads. Critical path per step:
// FSEL->FFMA->FSETP (12 cyc); zm1 = z-1 precomputed off-chain. Arithmetic
// grouping identical to the rel_err=0.0 kernels.

#define Bb    32
#define T     1024
#define Hh    512

#define HT      128            // h per block (= threads)
#define SROWS   32             // t-steps per stage
#define NSTAGE  4              // pipeline depth (64 KB smem total)
#define NST     (T / SROWS)    // 32 stages; last stage: 31 valid steps

__global__ __launch_bounds__(HT, 1)
void lif_kernel(const float* __restrict__ z, float* __restrict__ out) {
    __shared__ float sbuf[NSTAGE][SROWS][HT];   // 64 KB

    const int tid  = threadIdx.x;
    const int lane = tid & 31;
    const int wrp  = tid >> 5;
    const int b    = blockIdx.x >> 2;
    const int h0   = (blockIdx.x & 3) * HT;

    float* op = out + (size_t)b * T * Hh + h0 + tid;   // consumer column

    // loader granule: this thread loads 16B (4 cols at gcol) for rows
    // rbase + 4k, k = 0..7, within each stage.
    const int gcol  = wrp * 32 + (lane & 7) * 4;
    const int rbase = lane >> 3;                       // 0..3
    const float* zg = z + (size_t)b * T * Hh + h0 + gcol;

    // k = 0 output is zero (d_out poisoned).
    op[0] = 0.0f;

    // ── prologue: fill stages 0..NSTAGE-2 ────────────────────────────────
    #pragma unroll
    for (int s = 0; s < NSTAGE - 1; ++s) {
        #pragma unroll
        for (int k = 0; k < 8; ++k) {
            const int r = rbase + k * 4;
            __pipeline_memcpy_async(&sbuf[s][r][gcol],
                                    zg + (size_t)(s * SROWS + r) * Hh, 16);
        }
        __pipeline_commit();
    }

    float V = 0.0f;
    bool  p = false;    // reset predicate == previous spike

    for (int st = 0; st < NST; ++st) {
        __pipeline_wait_prior(NSTAGE - 2);   // my granules of stage st done
        __syncwarp();                        // visible warp-wide

        // refill stage st+NSTAGE-1 into the slot freed at stage st-1
        const int sn = st + NSTAGE - 1;
        if (sn < NST) {
            const int slot = sn & (NSTAGE - 1);
            #pragma unroll
            for (int k = 0; k < 8; ++k) {
                const int r = rbase + k * 4;
                __pipeline_memcpy_async(&sbuf[slot][r][gcol],
                                        zg + (size_t)(sn * SROWS + r) * Hh, 16);
            }
        }
        __pipeline_commit();                 // uniform group count

        const float* sp  = &sbuf[st & (NSTAGE - 1)][0][tid];
        float*       opk = op + (size_t)(st * SROWS + 1) * Hh;

        if (st < NST - 1) {
            #pragma unroll
            for (int r = 0; r < SROWS; ++r) {
                float zin = sp[r * HT];
                float zm1 = zin - 1.0f;           // off critical path
                float inj = p ? zm1 : zin;        // FSEL   (chain)
                V = fmaf(0.9f, V, inj);           // FFMA   (chain)
                p = V > 1.0f;                     // FSETP  (chain)
                opk[r * Hh] = p ? 1.0f : 0.0f;    // FSEL + STG (off-chain)
            }
        } else {
            #pragma unroll
            for (int r = 0; r < SROWS - 1; ++r) { // steps 993..1022
                float zin = sp[r * HT];
                float zm1 = zin - 1.0f;
                float inj = p ? zm1 : zin;
                V = fmaf(0.9f, V, inj);
                p = V > 1.0f;
                opk[r * Hh] = p ? 1.0f : 0.0f;
            }
        }
    }
}

extern "C" void kernel_launch(void* const* d_in, const int* in_sizes, int n_in,
                              void* d_out, int out_size) {
    const float* z = (const float*)d_in[0];
    float* out = (float*)d_out;
    lif_kernel<<<(Bb * Hh) / HT, HT>>>(z, out);
}

// round 11
// speedup vs baseline: 1.0483x; 1.0483x over previous
#include <cuda_runtime.h>
#include <cuda_pipeline.h>

// LIF scan — warp-local cp.async pipeline + chunked register prefetch.
//   out[b,0,h] = 0
//   for k=1..T-1: reset=(V>1); V = 0.9V + z[b,k-1,h] - reset; out[b,k,h] = (V>1)
//
// 1 thread <-> 1 (b,h) chain; 128 blocks x 128 threads (1 CTA/SM).
// Warp owns 32 contiguous h-cols; threads cp.async 16B granules cooperatively.
// Each 32-row stage is consumed in 8-step chunks with the next chunk's 8 LDS
// issued *before* consuming the current chunk: the 29-cyc LDS latency hides
// under the ~168-cyc compute chain of the current chunk and never lands on
// the carried FSEL->FFMA->FSETP cycle.

#define Bb    32
#define T     1024
#define Hh    512

#define HT      128            // h per block (= threads)
#define SROWS   32             // t-steps per stage
#define NSTAGE  4              // pipeline depth (64 KB smem)
#define NST     (T / SROWS)    // 32 stages; last stage: 31 valid steps
#define CH      8              // steps per register chunk

__global__ __launch_bounds__(HT, 1)
void lif_kernel(const float* __restrict__ z, float* __restrict__ out) {
    __shared__ float sbuf[NSTAGE][SROWS][HT];   // 64 KB

    const int tid  = threadIdx.x;
    const int lane = tid & 31;
    const int wrp  = tid >> 5;
    const int b    = blockIdx.x >> 2;
    const int h0   = (blockIdx.x & 3) * HT;

    float* op = out + (size_t)b * T * Hh + h0 + tid;   // consumer column

    // loader granule: 16B (4 cols) at gcol, rows rbase + 4k, k = 0..7
    const int gcol  = wrp * 32 + (lane & 7) * 4;
    const int rbase = lane >> 3;
    const float* zg = z + (size_t)b * T * Hh + h0 + gcol;

    op[0] = 0.0f;                 // k = 0 row (d_out poisoned)

    // ── prologue: fill stages 0..NSTAGE-2 ────────────────────────────────
    #pragma unroll
    for (int s = 0; s < NSTAGE - 1; ++s) {
        #pragma unroll
        for (int k = 0; k < 8; ++k) {
            const int r = rbase + k * 4;
            __pipeline_memcpy_async(&sbuf[s][r][gcol],
                                    zg + (size_t)(s * SROWS + r) * Hh, 16);
        }
        __pipeline_commit();
    }

    float V = 0.0f;
    bool  p = false;              // reset predicate == previous spike

    for (int st = 0; st < NST; ++st) {
        __pipeline_wait_prior(NSTAGE - 2);   // stage st resident
        __syncwarp();

        // refill stage st+NSTAGE-1
        const int sn = st + NSTAGE - 1;
        if (sn < NST) {
            const int slot = sn & (NSTAGE - 1);
            #pragma unroll
            for (int k = 0; k < 8; ++k) {
                const int r = rbase + k * 4;
                __pipeline_memcpy_async(&sbuf[slot][r][gcol],
                                        zg + (size_t)(sn * SROWS + r) * Hh, 16);
            }
        }
        __pipeline_commit();

        const float* sp  = &sbuf[st & (NSTAGE - 1)][0][tid];
        float*       opk = op + (size_t)(st * SROWS + 1) * Hh;

        // chunk 0 into registers (once-per-stage exposed LDS, amortized)
        float cur[CH];
        #pragma unroll
        for (int i = 0; i < CH; ++i) cur[i] = sp[i * HT];

        if (st < NST - 1) {
            #pragma unroll
            for (int c = 0; c < SROWS / CH; ++c) {
                float nxt[CH] = {0.f, 0.f, 0.f, 0.f, 0.f, 0.f, 0.f, 0.f};
                if (c < SROWS / CH - 1) {            // prefetch chunk c+1
                    #pragma unroll
                    for (int i = 0; i < CH; ++i)
                        nxt[i] = sp[((c + 1) * CH + i) * HT];
                }
                #pragma unroll
                for (int i = 0; i < CH; ++i) {       // consume chunk c
                    float zin = cur[i];
                    float zm1 = zin - 1.0f;          // off critical path
                    float inj = p ? zm1 : zin;       // FSEL   (chain)
                    V = fmaf(0.9f, V, inj);          // FFMA   (chain)
                    p = V > 1.0f;                    // FSETP  (chain)
                    opk[(c * CH + i) * Hh] = p ? 1.0f : 0.0f;
                }
                #pragma unroll
                for (int i = 0; i < CH; ++i) cur[i] = nxt[i];
            }
        } else {
            // last stage: 31 valid steps (chunks 8,8,8,7)
            #pragma unroll
            for (int c = 0; c < SROWS / CH; ++c) {
                float nxt[CH] = {0.f, 0.f, 0.f, 0.f, 0.f, 0.f, 0.f, 0.f};
                if (c < SROWS / CH - 1) {
                    #pragma unroll
                    for (int i = 0; i < CH; ++i)
                        nxt[i] = sp[((c + 1) * CH + i) * HT];
                }
                #pragma unroll
                for (int i = 0; i < CH; ++i) {
                    if (c * CH + i < SROWS - 1) {
                        float zin = cur[i];
                        float zm1 = zin - 1.0f;
                        float inj = p ? zm1 : zin;
                        V = fmaf(0.9f, V, inj);
                        p = V > 1.0f;
                        opk[(c * CH + i) * Hh] = p ? 1.0f : 0.0f;
                    }
                }
                #pragma unroll
                for (int i = 0; i < CH; ++i) cur[i] = nxt[i];
            }
        }
    }
}

extern "C" void kernel_launch(void* const* d_in, const int* in_sizes, int n_in,
                              void* d_out, int out_size) {
    const float* z = (const float*)d_in[0];
    float* out = (float*)d_out;
    lif_kernel<<<(Bb * Hh) / HT, HT>>>(z, out);
}